// round 13
// baseline (speedup 1.0000x reference)
#include <cuda_runtime.h>
#include <cuda_bf16.h>
#include <math.h>
#include <stdint.h>
#include <stddef.h>

// Problem constants
#define Bc 32
#define Tc 64
#define Sc 64
#define Vc 32000
#define Ec 512
#define Hc 512
#define KC 1536   // concat width = 2H + E

#define GRID_P 128   // persistent CTAs (<=148 SMs -> all co-resident)

// Output layout offsets (floats): outputs (B,T,V), h (2,B,H), c (2,B,H), attn (B,T,S)
#define OFF_H   ((size_t)Bc * Tc * Vc)
#define OFF_C   (OFF_H + (size_t)2 * Bc * Hc)
#define OFF_ATT (OFF_C + (size_t)2 * Bc * Hc)

// ---------------- device scratch (no allocations allowed) ----------------
__device__ float g_concat[(size_t)Tc * Bc * KC];   // [t][b][ h1 | ctx | emb ]
__device__ float g_c[2][Bc * Hc];                  // [layer][b*H+h]

// transposed [k][b] state for coalesced x-tile loads in the persistent kernel
__device__ float g_embT[Tc][Ec * Bc];
__device__ float g_ctxT[Hc * Bc];
__device__ float g_h0T[Hc * Bc];
__device__ float g_h1T[Hc * Bc];

// grid barrier state (sense-reversal; even barrier count per launch -> parity-safe)
__device__ int g_bar_cnt;
__device__ volatile int g_bar_sense;

// bf16 split operands for tensor-core vocab projection
__device__ __nv_bfloat16 g_Whi[(size_t)Vc * KC];
__device__ __nv_bfloat16 g_Wlo[(size_t)Vc * KC];
__device__ __nv_bfloat16 g_Ahi[(size_t)Tc * Bc * KC];
__device__ __nv_bfloat16 g_Alo[(size_t)Tc * Bc * KC];

// ---------------- init ----------------
__global__ void k_init(const float* __restrict__ h0, const float* __restrict__ c0) {
    int i = blockIdx.x * blockDim.x + threadIdx.x;
    if (i < Bc * Hc) {
        int h = i & (Hc - 1), b = i >> 9;
        g_h0T[h * Bc + b] = h0[i];
        g_h1T[h * Bc + b] = h0[Bc * Hc + i];
        g_c[0][i] = c0[i];
        g_c[1][i] = c0[Bc * Hc + i];
    }
}

// ---------------- embedding gathers ----------------
__global__ void k_embed(const int* __restrict__ tok, const float* __restrict__ emb) {
    int r = blockIdx.x;          // r = t*32 + b
    int t = r >> 5, b = r & 31;
    int tk = tok[b * Tc + t];
    const float4* src = (const float4*)(emb + (size_t)tk * Ec);
    float4* dst = (float4*)(g_concat + (size_t)r * KC + 2 * Hc);
    for (int i = threadIdx.x; i < Ec / 4; i += blockDim.x) dst[i] = src[i];
}

__global__ void k_embed2(const int* __restrict__ tok, const float* __restrict__ emb) {
    int r = blockIdx.x;          // r = t*32 + b
    int t = r >> 5, b = r & 31;
    int tk = tok[b * Tc + t];
    const float* src = emb + (size_t)tk * Ec;
    for (int k = threadIdx.x; k < Ec; k += blockDim.x)
        g_embT[t][k * Bc + b] = src[k];
}

// ---------------- split-bf16 conversion kernels ----------------
__global__ void k_cvtW(const float* __restrict__ src) {
    size_t i = ((size_t)blockIdx.x * 256 + threadIdx.x) * 4;
    float4 v = *(const float4*)(src + i);
    __nv_bfloat16 h0 = __float2bfloat16(v.x), h1 = __float2bfloat16(v.y);
    __nv_bfloat16 h2 = __float2bfloat16(v.z), h3 = __float2bfloat16(v.w);
    __nv_bfloat16 l0 = __float2bfloat16(v.x - __bfloat162float(h0));
    __nv_bfloat16 l1 = __float2bfloat16(v.y - __bfloat162float(h1));
    __nv_bfloat16 l2 = __float2bfloat16(v.z - __bfloat162float(h2));
    __nv_bfloat16 l3 = __float2bfloat16(v.w - __bfloat162float(h3));
    *(__nv_bfloat162*)&g_Whi[i]     = __halves2bfloat162(h0, h1);
    *(__nv_bfloat162*)&g_Whi[i + 2] = __halves2bfloat162(h2, h3);
    *(__nv_bfloat162*)&g_Wlo[i]     = __halves2bfloat162(l0, l1);
    *(__nv_bfloat162*)&g_Wlo[i + 2] = __halves2bfloat162(l2, l3);
}

__global__ void k_cvtA() {
    size_t i = ((size_t)blockIdx.x * 256 + threadIdx.x) * 4;
    float4 v = *(const float4*)(g_concat + i);
    __nv_bfloat16 h0 = __float2bfloat16(v.x), h1 = __float2bfloat16(v.y);
    __nv_bfloat16 h2 = __float2bfloat16(v.z), h3 = __float2bfloat16(v.w);
    __nv_bfloat16 l0 = __float2bfloat16(v.x - __bfloat162float(h0));
    __nv_bfloat16 l1 = __float2bfloat16(v.y - __bfloat162float(h1));
    __nv_bfloat16 l2 = __float2bfloat16(v.z - __bfloat162float(h2));
    __nv_bfloat16 l3 = __float2bfloat16(v.w - __bfloat162float(h3));
    *(__nv_bfloat162*)&g_Ahi[i]     = __halves2bfloat162(h0, h1);
    *(__nv_bfloat162*)&g_Ahi[i + 2] = __halves2bfloat162(h2, h3);
    *(__nv_bfloat162*)&g_Alo[i]     = __halves2bfloat162(l0, l1);
    *(__nv_bfloat162*)&g_Alo[i + 2] = __halves2bfloat162(l2, l3);
}

// ---------------- grid barrier: atomic arrive, volatile-load poll ----------------
__device__ __forceinline__ void gbar(int& sense) {
    __syncthreads();
    if (threadIdx.x == 0) {
        __threadfence();                              // release
        int t = atomicAdd(&g_bar_cnt, 1);
        if (t == GRID_P - 1) {
            g_bar_cnt = 0;
            __threadfence();
            g_bar_sense = sense ^ 1;                  // volatile store
        } else {
            while (g_bar_sense == sense) __nanosleep(32);   // volatile load poll (no atomics)
        }
        __threadfence();                              // acquire
    }
    __syncthreads();
    sense ^= 1;
}

// ---------------- persistent recurrence kernel ----------------
// 128 CTAs x 256 threads. Per step: P1 attn (CTAs 0..31) | P2 L0 full GEMM+gates |
// P3 L1 full GEMM+gates.  3 grid barriers/step.  No split-K: each CTA owns
// 4 hidden units x 4 gates (16 j rows), K split 8-way ACROSS WARPS inside the
// CTA and reduced in shared memory.  Each CTA touches the same W slice every
// step -> L1-resident.  Cross-CTA mutable reads use __ldcg.
__global__ __launch_bounds__(256) void k_recur(
    const float* __restrict__ enc,
    const float* __restrict__ Wih0, const float* __restrict__ Whh0,
    const float* __restrict__ bih0, const float* __restrict__ bhh0,
    const float* __restrict__ Wih1, const float* __restrict__ Whh1,
    const float* __restrict__ bih1, const float* __restrict__ bhh1,
    float* __restrict__ out)
{
    __shared__ float xs[128 * 36];    // x tile [k][b], stride 36 (16B-aligned float4 rows)
    __shared__ float ws[128 * 20];    // W tile [k][j_local], stride 20
    __shared__ float part[8 * 512];   // per-warp k-slice partials [ks][jl*32+b]; doubles as q-scratch in P1
    __shared__ float sc[Sc], sa[Sc];

    const int bid = blockIdx.x;
    const int tid = threadIdx.x, w = tid >> 5, lane = tid & 31;
    const int bg = tid & 7;           // 4 b each
    const int jg = (tid >> 3) & 3;    // 4 j each
    const int jl_st = tid >> 4;       // staging j-local 0..15
    const int kk_st = (tid & 15) * 8; // staging k offset within tile
    int sense = 0;

    for (int t = 0; t < Tc; t++) {
        // ---------- P1: attention (CTAs 0..31, b = bid) ----------
        if (bid < Bc) {
            int b = bid;
            float* qs = part;   // 512 floats scratch
            for (int i = tid; i < Hc; i += 256) qs[i] = __ldcg(&g_h1T[i * Bc + b]);
            __syncthreads();
            const float* encb = enc + (size_t)b * Sc * Hc;
            #pragma unroll
            for (int i = 0; i < 8; i++) {
                int s = w * 8 + i;
                const float* e = encb + (size_t)s * Hc;
                float acc = 0.f;
                for (int h = lane; h < Hc; h += 32) acc += qs[h] * e[h];
                #pragma unroll
                for (int o = 16; o; o >>= 1) acc += __shfl_down_sync(0xffffffffu, acc, o);
                if (lane == 0) sc[s] = acc * 0.04419417382415922f;  // 1/sqrt(512)
            }
            __syncthreads();
            if (w == 0) {
                float v0 = sc[lane], v1 = sc[lane + 32];
                float m = fmaxf(v0, v1);
                #pragma unroll
                for (int o = 16; o; o >>= 1) m = fmaxf(m, __shfl_xor_sync(0xffffffffu, m, o));
                float e0 = expf(v0 - m), e1 = expf(v1 - m);
                float ssum = e0 + e1;
                #pragma unroll
                for (int o = 16; o; o >>= 1) ssum += __shfl_xor_sync(0xffffffffu, ssum, o);
                float inv = 1.f / ssum;
                sa[lane] = e0 * inv;
                sa[lane + 32] = e1 * inv;
            }
            __syncthreads();
            if (tid < Sc) out[OFF_ATT + (size_t)b * Tc * Sc + (size_t)t * Sc + tid] = sa[tid];
            for (int h = tid; h < Hc; h += 256) {
                float acc = 0.f;
                #pragma unroll 8
                for (int s = 0; s < Sc; s++) acc += sa[s] * encb[(size_t)s * Hc + h];
                g_ctxT[h * Bc + b] = acc;
                g_concat[((size_t)(t * Bc + b)) * KC + Hc + h] = acc;
            }
        }
        gbar(sense);

        // ---------- P2 / P3: full-K LSTM layer (GEMM + gates), one barrier each ----------
        #pragma unroll 1
        for (int layer = 0; layer < 2; layer++) {
            const int NT = layer ? 8 : 12;     // k-tiles of 128 (K = 1024 / 1536)
            // W row for staging: j = gate*512 + bid*4 + hl
            const int jrow = ((jl_st >> 2) << 9) + (bid << 2) + (jl_st & 3);
            float acc[4][4] = {};

            for (int kt = 0; kt < NT; kt++) {
                const int k0 = kt * 128;
                // stage x tile: warp w stages rows [w*16, w*16+16)
                #pragma unroll
                for (int p = 0; p < 4; p++) {
                    int r = w * 16 + p * 4 + (lane >> 3);
                    int c4 = (lane & 7) * 4;
                    int gk = k0 + r;
                    const float* src;
                    if (layer == 0) {
                        if (gk < Ec)            src = &g_embT[t][gk * Bc];
                        else if (gk < 2 * Hc)   src = &g_ctxT[(gk - Ec) * Bc];
                        else                    src = &g_h0T[(gk - 2 * Hc) * Bc];
                    } else {
                        src = (gk < Hc) ? &g_h0T[gk * Bc] : &g_h1T[(gk - Hc) * Bc];
                    }
                    *(float4*)&xs[r * 36 + c4] = __ldcg((const float4*)&src[c4]);
                }
                // stage W tile: 16 j x 128 k, thread loads 8 consecutive k of one j
                {
                    int gk = k0 + kk_st;
                    const float* wr;
                    if (layer == 0)
                        wr = (gk < Ec + Hc) ? (Wih0 + (size_t)jrow * (Ec + Hc) + gk)
                                            : (Whh0 + (size_t)jrow * Hc + gk - Ec - Hc);
                    else
                        wr = (gk < Hc) ? (Wih1 + (size_t)jrow * Hc + gk)
                                       : (Whh1 + (size_t)jrow * Hc + gk - Hc);
                    float4 a = __ldg((const float4*)wr);
                    float4 b4 = __ldg((const float4*)(wr + 4));
                    ws[(kk_st + 0) * 20 + jl_st] = a.x;
                    ws[(kk_st + 1) * 20 + jl_st] = a.y;
                    ws[(kk_st + 2) * 20 + jl_st] = a.z;
                    ws[(kk_st + 3) * 20 + jl_st] = a.w;
                    ws[(kk_st + 4) * 20 + jl_st] = b4.x;
                    ws[(kk_st + 5) * 20 + jl_st] = b4.y;
                    ws[(kk_st + 6) * 20 + jl_st] = b4.z;
                    ws[(kk_st + 7) * 20 + jl_st] = b4.w;
                }
                __syncthreads();
                // compute: warp w consumes its own rows [w*16, w*16+16)
                #pragma unroll
                for (int kk = 0; kk < 16; kk++) {
                    int r = w * 16 + kk;
                    float4 xv = *(const float4*)&xs[r * 36 + bg * 4];
                    float4 wv = *(const float4*)&ws[r * 20 + jg * 4];
                    acc[0][0] += wv.x * xv.x; acc[0][1] += wv.x * xv.y; acc[0][2] += wv.x * xv.z; acc[0][3] += wv.x * xv.w;
                    acc[1][0] += wv.y * xv.x; acc[1][1] += wv.y * xv.y; acc[1][2] += wv.y * xv.z; acc[1][3] += wv.y * xv.w;
                    acc[2][0] += wv.z * xv.x; acc[2][1] += wv.z * xv.y; acc[2][2] += wv.z * xv.z; acc[2][3] += wv.z * xv.w;
                    acc[3][0] += wv.w * xv.x; acc[3][1] += wv.w * xv.y; acc[3][2] += wv.w * xv.z; acc[3][3] += wv.w * xv.w;
                }
                __syncthreads();
            }

            // intra-CTA k-slice reduction via smem
            #pragma unroll
            for (int ji = 0; ji < 4; ji++)
                *(float4*)&part[w * 512 + (jg * 4 + ji) * 32 + bg * 4] =
                    make_float4(acc[ji][0], acc[ji][1], acc[ji][2], acc[ji][3]);
            __syncthreads();

            // gates + state update: 128 cells (4 h-units x 32 b)
            if (tid < 128) {
                int hl = tid >> 5, b = tid & 31;
                const float* bi = layer ? bih1 : bih0;
                const float* bh = layer ? bhh1 : bhh0;
                float gg[4];
                #pragma unroll
                for (int g4 = 0; g4 < 4; g4++) {
                    int j = (g4 << 9) + (bid << 2) + hl;
                    float s = bi[j] + bh[j];
                    int jl = g4 * 4 + hl;
                    #pragma unroll
                    for (int ksl = 0; ksl < 8; ksl++)
                        s += part[ksl * 512 + jl * 32 + b];
                    gg[g4] = s;
                }
                int h = (bid << 2) + hl;
                float* cptr = &g_c[layer][b * Hc + h];
                float cold = *cptr;                 // cell owned by this CTA every step
                float i_ = 1.f / (1.f + expf(-gg[0]));
                float f_ = 1.f / (1.f + expf(-gg[1]));
                float gv = tanhf(gg[2]);
                float o_ = 1.f / (1.f + expf(-gg[3]));
                float cn = f_ * cold + i_ * gv;
                float hn = o_ * tanhf(cn);
                *cptr = cn;
                if (layer == 0) {
                    g_h0T[h * Bc + b] = hn;
                } else {
                    g_h1T[h * Bc + b] = hn;
                    g_concat[((size_t)(t * Bc + b)) * KC + h] = hn;
                }
            }
            gbar(sense);
        }
    }
}

// ---------------- tensor-core vocab projection: split-bf16, 3-product ----------------
__device__ __forceinline__ void mma_bf16(float c[4], const uint32_t a[4], const uint32_t b[2]) {
    asm volatile("mma.sync.aligned.m16n8k16.row.col.f32.bf16.bf16.f32 "
                 "{%0,%1,%2,%3}, {%4,%5,%6,%7}, {%8,%9}, {%0,%1,%2,%3};"
                 : "+f"(c[0]), "+f"(c[1]), "+f"(c[2]), "+f"(c[3])
                 : "r"(a[0]), "r"(a[1]), "r"(a[2]), "r"(a[3]), "r"(b[0]), "r"(b[1]));
}

__global__ __launch_bounds__(256) void k_mma(const float* __restrict__ bias,
                                             float* __restrict__ out) {
    __shared__ __nv_bfloat16 As[2][64 * 48];
    __shared__ __nv_bfloat16 Bs[2][128 * 48];
    int m0 = blockIdx.x * 64;
    int n0 = blockIdx.y * 128;
    int tid = threadIdx.x, lane = tid & 31, wid = tid >> 5;
    int wm = wid & 1, wn = wid >> 1;
    int g = lane >> 2, q2 = (lane & 3) * 2;

    float acc[2][4][4];
    #pragma unroll
    for (int i = 0; i < 2; i++)
        #pragma unroll
        for (int j = 0; j < 4; j++)
            #pragma unroll
            for (int q = 0; q < 4; q++) acc[i][j][q] = 0.f;

    int arow = tid >> 2, akc = (tid & 3) * 8;

    for (int kt = 0; kt < KC / 32; kt++) {
        int k0 = kt * 32;
        *(uint4*)&As[0][arow * 48 + akc] = *(const uint4*)&g_Ahi[(size_t)(m0 + arow) * KC + k0 + akc];
        *(uint4*)&As[1][arow * 48 + akc] = *(const uint4*)&g_Alo[(size_t)(m0 + arow) * KC + k0 + akc];
        #pragma unroll
        for (int i = 0; i < 2; i++) {
            int idx = i * 256 + tid;
            int n = idx >> 2, kc = (idx & 3) * 8;
            *(uint4*)&Bs[0][n * 48 + kc] = *(const uint4*)&g_Whi[(size_t)(n0 + n) * KC + k0 + kc];
            *(uint4*)&Bs[1][n * 48 + kc] = *(const uint4*)&g_Wlo[(size_t)(n0 + n) * KC + k0 + kc];
        }
        __syncthreads();

        #pragma unroll
        for (int ks = 0; ks < 32; ks += 16) {
            uint32_t ah[2][4], al[2][4], bh[4][2], bl[4][2];
            #pragma unroll
            for (int m2 = 0; m2 < 2; m2++) {
                int rm = wm * 32 + m2 * 16;
                ah[m2][0] = *(uint32_t*)&As[0][(rm + g) * 48 + ks + q2];
                ah[m2][1] = *(uint32_t*)&As[0][(rm + 8 + g) * 48 + ks + q2];
                ah[m2][2] = *(uint32_t*)&As[0][(rm + g) * 48 + ks + 8 + q2];
                ah[m2][3] = *(uint32_t*)&As[0][(rm + 8 + g) * 48 + ks + 8 + q2];
                al[m2][0] = *(uint32_t*)&As[1][(rm + g) * 48 + ks + q2];
                al[m2][1] = *(uint32_t*)&As[1][(rm + 8 + g) * 48 + ks + q2];
                al[m2][2] = *(uint32_t*)&As[1][(rm + g) * 48 + ks + 8 + q2];
                al[m2][3] = *(uint32_t*)&As[1][(rm + 8 + g) * 48 + ks + 8 + q2];
            }
            #pragma unroll
            for (int n4 = 0; n4 < 4; n4++) {
                int cn = wn * 32 + n4 * 8;
                bh[n4][0] = *(uint32_t*)&Bs[0][(cn + g) * 48 + ks + q2];
                bh[n4][1] = *(uint32_t*)&Bs[0][(cn + g) * 48 + ks + 8 + q2];
                bl[n4][0] = *(uint32_t*)&Bs[1][(cn + g) * 48 + ks + q2];
                bl[n4][1] = *(uint32_t*)&Bs[1][(cn + g) * 48 + ks + 8 + q2];
            }
            #pragma unroll
            for (int m2 = 0; m2 < 2; m2++)
                #pragma unroll
                for (int n4 = 0; n4 < 4; n4++) {
                    mma_bf16(acc[m2][n4], ah[m2], bh[n4]);
                    mma_bf16(acc[m2][n4], ah[m2], bl[n4]);
                    mma_bf16(acc[m2][n4], al[m2], bh[n4]);
                }
        }
        __syncthreads();
    }

    #pragma unroll
    for (int m2 = 0; m2 < 2; m2++)
        #pragma unroll
        for (int n4 = 0; n4 < 4; n4++) {
            int gm = m0 + wm * 32 + m2 * 16 + g;
            int gn = n0 + wn * 32 + n4 * 8 + q2;
            float bb0 = bias[gn], bb1 = bias[gn + 1];
            int t0 = gm >> 5, b0 = gm & 31;
            float2 v0 = make_float2(acc[m2][n4][0] + bb0, acc[m2][n4][1] + bb1);
            *(float2*)&out[(size_t)b0 * Tc * Vc + (size_t)t0 * Vc + gn] = v0;
            int gm8 = gm + 8;
            int t1 = gm8 >> 5, b1 = gm8 & 31;
            float2 v1 = make_float2(acc[m2][n4][2] + bb0, acc[m2][n4][3] + bb1);
            *(float2*)&out[(size_t)b1 * Tc * Vc + (size_t)t1 * Vc + gn] = v1;
        }
}

// ---------------- final state copy ----------------
__global__ void k_final(float* __restrict__ out) {
    int i = blockIdx.x * blockDim.x + threadIdx.x;
    if (i < Bc * Hc) {
        int h = i & (Hc - 1), b = i >> 9;
        out[OFF_H + i] = g_h0T[h * Bc + b];
        out[OFF_H + Bc * Hc + i] = g_h1T[h * Bc + b];
        out[OFF_C + i] = g_c[0][i];
        out[OFF_C + Bc * Hc + i] = g_c[1][i];
    }
}

// ---------------- launch ----------------
extern "C" void kernel_launch(void* const* d_in, const int* in_sizes, int n_in,
                              void* d_out, int out_size) {
    int idx_emb = -1, idx_enc = -1, idx_h0 = -1;
    for (int i = 0; i < n_in; i++) {
        if (in_sizes[i] == 16384000) { idx_emb = i; break; }
    }
    for (int i = 0; i < n_in; i++) {
        if (in_sizes[i] == 1048576) { idx_enc = i; break; }
    }
    for (int i = 0; i < n_in; i++) {
        if (in_sizes[i] == 32768) { idx_h0 = i; break; }
    }
    const int*   tok  = (const int*)d_in[0];
    const float* enc  = (const float*)d_in[idx_enc];
    const float* h0   = (const float*)d_in[idx_h0];
    const float* c0   = (const float*)d_in[idx_h0 + 1];
    const float* emb  = (const float*)d_in[idx_emb];
    const float* Wih0 = (const float*)d_in[idx_emb + 1];
    const float* Whh0 = (const float*)d_in[idx_emb + 2];
    const float* bih0 = (const float*)d_in[idx_emb + 3];
    const float* bhh0 = (const float*)d_in[idx_emb + 4];
    const float* Wih1 = (const float*)d_in[idx_emb + 5];
    const float* Whh1 = (const float*)d_in[idx_emb + 6];
    const float* bih1 = (const float*)d_in[idx_emb + 7];
    const float* bhh1 = (const float*)d_in[idx_emb + 8];
    const float* fcW  = (const float*)d_in[idx_emb + 9];
    const float* fcb  = (const float*)d_in[idx_emb + 10];
    float* out = (float*)d_out;

    k_cvtW<<<48000, 256>>>(fcW);

    k_init<<<(Bc * Hc + 255) / 256, 256>>>(h0, c0);
    k_embed<<<Tc * Bc, 128>>>(tok, emb);    // concat emb section (for cvtA)
    k_embed2<<<Tc * Bc, 128>>>(tok, emb);   // transposed emb (for recurrence)

    // whole recurrence in ONE persistent kernel (128 co-resident CTAs, 3 barriers/step)
    k_recur<<<GRID_P, 256>>>(enc, Wih0, Whh0, bih0, bhh0,
                             Wih1, Whh1, bih1, bhh1, out);

    k_cvtA<<<3072, 256>>>();
    k_mma<<<dim3(Tc * Bc / 64, Vc / 128), 256>>>(fcb, out);
    k_final<<<(Bc * Hc + 255) / 256, 256>>>(out);
}

// round 14
// speedup vs baseline: 1.0500x; 1.0500x over previous
#include <cuda_runtime.h>
#include <cuda_bf16.h>
#include <math.h>
#include <stdint.h>
#include <stddef.h>

// Problem constants
#define Bc 32
#define Tc 64
#define Sc 64
#define Vc 32000
#define Ec 512
#define Hc 512
#define KC 1536   // concat width = 2H + E

#define GRID_P 128   // persistent CTAs (<=148 SMs -> all co-resident)

// Output layout offsets (floats): outputs (B,T,V), h (2,B,H), c (2,B,H), attn (B,T,S)
#define OFF_H   ((size_t)Bc * Tc * Vc)
#define OFF_C   (OFF_H + (size_t)2 * Bc * Hc)
#define OFF_ATT (OFF_C + (size_t)2 * Bc * Hc)

// ---------------- device scratch (no allocations allowed) ----------------
__device__ float g_concat[(size_t)Tc * Bc * KC];   // [t][b][ h1 | ctx | emb ]
__device__ float g_part[8 * 2048 * Bc];            // split-K partials [seg][j][b]
__device__ float g_c[2][Bc * Hc];                  // [layer][b*H+h]

// ping-pong transposed [k][b] state (read pr, write nx) — needed because gate
// updates are fused into the partials phase (write overlaps other CTAs' reads)
__device__ float g_embT[Tc][Ec * Bc];
__device__ float g_ctxT[Hc * Bc];
__device__ float g_h0T[2][Hc * Bc];
__device__ float g_h1T[2][Hc * Bc];

__device__ int g_cnt[16];            // per-chunk last-block counters (self-reset)
__device__ int g_bar_cnt;            // grid barrier
__device__ volatile int g_bar_sense;

// bf16 split operands for tensor-core vocab projection
__device__ __nv_bfloat16 g_Whi[(size_t)Vc * KC];
__device__ __nv_bfloat16 g_Wlo[(size_t)Vc * KC];
__device__ __nv_bfloat16 g_Ahi[(size_t)Tc * Bc * KC];
__device__ __nv_bfloat16 g_Alo[(size_t)Tc * Bc * KC];

// ---------------- init ----------------
__global__ void k_init(const float* __restrict__ h0, const float* __restrict__ c0) {
    int i = blockIdx.x * blockDim.x + threadIdx.x;
    if (i < Bc * Hc) {
        int h = i & (Hc - 1), b = i >> 9;
        g_h0T[0][h * Bc + b] = h0[i];
        g_h1T[0][h * Bc + b] = h0[Bc * Hc + i];
        g_c[0][i] = c0[i];
        g_c[1][i] = c0[Bc * Hc + i];
    }
}

// ---------------- embedding gathers ----------------
__global__ void k_embed(const int* __restrict__ tok, const float* __restrict__ emb) {
    int r = blockIdx.x;          // r = t*32 + b
    int t = r >> 5, b = r & 31;
    int tk = tok[b * Tc + t];
    const float4* src = (const float4*)(emb + (size_t)tk * Ec);
    float4* dst = (float4*)(g_concat + (size_t)r * KC + 2 * Hc);
    for (int i = threadIdx.x; i < Ec / 4; i += blockDim.x) dst[i] = src[i];
}

__global__ void k_embed2(const int* __restrict__ tok, const float* __restrict__ emb) {
    int r = blockIdx.x;          // r = t*32 + b
    int t = r >> 5, b = r & 31;
    int tk = tok[b * Tc + t];
    const float* src = emb + (size_t)tk * Ec;
    for (int k = threadIdx.x; k < Ec; k += blockDim.x)
        g_embT[t][k * Bc + b] = src[k];
}

// ---------------- split-bf16 conversion kernels ----------------
__global__ void k_cvtW(const float* __restrict__ src) {
    size_t i = ((size_t)blockIdx.x * 256 + threadIdx.x) * 4;
    float4 v = *(const float4*)(src + i);
    __nv_bfloat16 h0 = __float2bfloat16(v.x), h1 = __float2bfloat16(v.y);
    __nv_bfloat16 h2 = __float2bfloat16(v.z), h3 = __float2bfloat16(v.w);
    __nv_bfloat16 l0 = __float2bfloat16(v.x - __bfloat162float(h0));
    __nv_bfloat16 l1 = __float2bfloat16(v.y - __bfloat162float(h1));
    __nv_bfloat16 l2 = __float2bfloat16(v.z - __bfloat162float(h2));
    __nv_bfloat16 l3 = __float2bfloat16(v.w - __bfloat162float(h3));
    *(__nv_bfloat162*)&g_Whi[i]     = __halves2bfloat162(h0, h1);
    *(__nv_bfloat162*)&g_Whi[i + 2] = __halves2bfloat162(h2, h3);
    *(__nv_bfloat162*)&g_Wlo[i]     = __halves2bfloat162(l0, l1);
    *(__nv_bfloat162*)&g_Wlo[i + 2] = __halves2bfloat162(l2, l3);
}

__global__ void k_cvtA() {
    size_t i = ((size_t)blockIdx.x * 256 + threadIdx.x) * 4;
    float4 v = *(const float4*)(g_concat + i);
    __nv_bfloat16 h0 = __float2bfloat16(v.x), h1 = __float2bfloat16(v.y);
    __nv_bfloat16 h2 = __float2bfloat16(v.z), h3 = __float2bfloat16(v.w);
    __nv_bfloat16 l0 = __float2bfloat16(v.x - __bfloat162float(h0));
    __nv_bfloat16 l1 = __float2bfloat16(v.y - __bfloat162float(h1));
    __nv_bfloat16 l2 = __float2bfloat16(v.z - __bfloat162float(h2));
    __nv_bfloat16 l3 = __float2bfloat16(v.w - __bfloat162float(h3));
    *(__nv_bfloat162*)&g_Ahi[i]     = __halves2bfloat162(h0, h1);
    *(__nv_bfloat162*)&g_Ahi[i + 2] = __halves2bfloat162(h2, h3);
    *(__nv_bfloat162*)&g_Alo[i]     = __halves2bfloat162(l0, l1);
    *(__nv_bfloat162*)&g_Alo[i + 2] = __halves2bfloat162(l2, l3);
}

// ---------------- grid barrier: atomic arrive, VOLATILE-LOAD poll ----------------
__device__ __forceinline__ void gbar(int& sense) {
    __syncthreads();
    if (threadIdx.x == 0) {
        __threadfence();                              // release
        int t = atomicAdd(&g_bar_cnt, 1);
        if (t == GRID_P - 1) {
            g_bar_cnt = 0;
            __threadfence();
            g_bar_sense = sense ^ 1;                  // volatile store (release)
        } else {
            while (g_bar_sense == sense) __nanosleep(64);  // parallel L2 reads, no RMW
        }
        __threadfence();                              // acquire
    }
    __syncthreads();
    sense ^= 1;
}

// ---------------- persistent recurrence kernel ----------------
// R11's proven split-K layout (chunk = bid&15 -> 32 h-units x 4 gates; seg =
// bid>>4 -> 1/8 of K), but gates FUSED into the partials phase via a per-chunk
// last-block counter (R9 pattern) -> only 3 grid barriers per step:
//   P1 attn | P2 L0 partials+gates | P3 L1 partials+gates
// h-state is ping-pong buffered (read pr, write nx) to make the fused gate
// writes race-free against other CTAs' x staging.
__global__ __launch_bounds__(256) void k_recur(
    const float* __restrict__ enc,
    const float* __restrict__ Wih0, const float* __restrict__ Whh0,
    const float* __restrict__ bih0, const float* __restrict__ bhh0,
    const float* __restrict__ Wih1, const float* __restrict__ Whh1,
    const float* __restrict__ bih1, const float* __restrict__ bhh1,
    float* __restrict__ out)
{
    __shared__ float xs[192 * 33];    // x tile [k][b] (L0: 192 rows, L1: 128)
    __shared__ float wsT[32 * 129];   // W sub-tile [k][j_local]; q-scratch in P1
    __shared__ float sc[Sc], sa[Sc];
    __shared__ int slast;

    const int bid = blockIdx.x;
    const int tid = threadIdx.x, w = tid >> 5, lane = tid & 31;
    const int bq = tid & 7;      // b-group (4 b each)
    const int jq = tid >> 3;     // j-group (4 j each, 0..31)
    const int chunk = bid & 15;  // 32 hidden units x 4 gates = 128 j rows
    const int seg = bid >> 4;    // k-segment 0..7
    int sense = 0;

    for (int t = 0; t < Tc; t++) {
        const int pr = t & 1, nx = pr ^ 1;

        // ---------- P1: attention (CTAs 0..31, b = bid) ----------
        if (bid < Bc) {
            int b = bid;
            float* qs = wsT;   // 512 floats scratch
            for (int i = tid; i < Hc; i += 256) qs[i] = __ldcg(&g_h1T[pr][i * Bc + b]);
            __syncthreads();
            const float* encb = enc + (size_t)b * Sc * Hc;
            #pragma unroll
            for (int i = 0; i < 8; i++) {
                int s = w * 8 + i;
                const float* e = encb + (size_t)s * Hc;
                float acc = 0.f;
                for (int h = lane; h < Hc; h += 32) acc += qs[h] * e[h];
                #pragma unroll
                for (int o = 16; o; o >>= 1) acc += __shfl_down_sync(0xffffffffu, acc, o);
                if (lane == 0) sc[s] = acc * 0.04419417382415922f;  // 1/sqrt(512)
            }
            __syncthreads();
            if (w == 0) {
                float v0 = sc[lane], v1 = sc[lane + 32];
                float m = fmaxf(v0, v1);
                #pragma unroll
                for (int o = 16; o; o >>= 1) m = fmaxf(m, __shfl_xor_sync(0xffffffffu, m, o));
                float e0 = expf(v0 - m), e1 = expf(v1 - m);
                float ssum = e0 + e1;
                #pragma unroll
                for (int o = 16; o; o >>= 1) ssum += __shfl_xor_sync(0xffffffffu, ssum, o);
                float inv = 1.f / ssum;
                sa[lane] = e0 * inv;
                sa[lane + 32] = e1 * inv;
            }
            __syncthreads();
            if (tid < Sc) out[OFF_ATT + (size_t)b * Tc * Sc + (size_t)t * Sc + tid] = sa[tid];
            for (int h = tid; h < Hc; h += 256) {
                float acc = 0.f;
                #pragma unroll 8
                for (int s = 0; s < Sc; s++) acc += sa[s] * encb[(size_t)s * Hc + h];
                g_ctxT[h * Bc + b] = acc;
                g_concat[((size_t)(t * Bc + b)) * KC + Hc + h] = acc;
            }
        }
        gbar(sense);

        // ---------- P2 / P3: split-K partials + fused last-block gates ----------
        #pragma unroll 1
        for (int layer = 0; layer < 2; layer++) {
            const int KSEG = (layer == 0) ? 192 : 128;
            const int k0 = seg * KSEG;

            // stage x tile rows (coalesced: 32 consecutive b per k-row)
            for (int r = w; r < KSEG; r += 8) {
                int gk = k0 + r;
                const float* src;
                if (layer == 0) {
                    if (gk < Ec)            src = &g_embT[t][gk * Bc];
                    else if (gk < Ec + Hc)  src = &g_ctxT[(gk - Ec) * Bc];
                    else                    src = &g_h0T[pr][(gk - Ec - Hc) * Bc];
                } else {
                    src = (gk < Hc) ? &g_h0T[nx][gk * Bc] : &g_h1T[pr][(gk - Hc) * Bc];
                }
                xs[r * 33 + lane] = __ldcg(&src[lane]);
            }

            float acc[4][4] = {};
            const int nkt = KSEG / 32;
            for (int kt = 0; kt < nkt; kt++) {
                __syncthreads();
                int gk = k0 + kt * 32;   // 32-aligned; never crosses weight boundary
                const float* wptr; int wstr;
                if (layer == 0) {
                    if (gk < Ec + Hc) { wptr = Wih0 + gk;              wstr = Ec + Hc; }
                    else              { wptr = Whh0 + (gk - Ec - Hc);  wstr = Hc; }
                } else {
                    if (gk < Hc)      { wptr = Wih1 + gk;              wstr = Hc; }
                    else              { wptr = Whh1 + (gk - Hc);       wstr = Hc; }
                }
                #pragma unroll
                for (int i = 0; i < 16; i++) {
                    int jl = w * 16 + i;
                    int j = ((jl >> 5) << 9) + (chunk << 5) + (jl & 31);
                    wsT[lane * 129 + jl] = wptr[(size_t)j * wstr + lane];
                }
                __syncthreads();
                #pragma unroll
                for (int kk = 0; kk < 32; kk++) {
                    int kg = kt * 32 + kk;
                    float xv0 = xs[kg * 33 + 4 * bq + 0], xv1 = xs[kg * 33 + 4 * bq + 1];
                    float xv2 = xs[kg * 33 + 4 * bq + 2], xv3 = xs[kg * 33 + 4 * bq + 3];
                    float wv0 = wsT[kk * 129 + 4 * jq + 0], wv1 = wsT[kk * 129 + 4 * jq + 1];
                    float wv2 = wsT[kk * 129 + 4 * jq + 2], wv3 = wsT[kk * 129 + 4 * jq + 3];
                    acc[0][0] += wv0 * xv0; acc[0][1] += wv0 * xv1; acc[0][2] += wv0 * xv2; acc[0][3] += wv0 * xv3;
                    acc[1][0] += wv1 * xv0; acc[1][1] += wv1 * xv1; acc[1][2] += wv1 * xv2; acc[1][3] += wv1 * xv3;
                    acc[2][0] += wv2 * xv0; acc[2][1] += wv2 * xv1; acc[2][2] += wv2 * xv2; acc[2][3] += wv2 * xv3;
                    acc[3][0] += wv3 * xv0; acc[3][1] += wv3 * xv1; acc[3][2] += wv3 * xv2; acc[3][3] += wv3 * xv3;
                }
            }

            // write partials g_part[seg][j][b]
            #pragma unroll
            for (int ji = 0; ji < 4; ji++) {
                int jl = 4 * jq + ji;
                int j = ((jl >> 5) << 9) + (chunk << 5) + (jl & 31);
                float4 v = make_float4(acc[ji][0], acc[ji][1], acc[ji][2], acc[ji][3]);
                *(float4*)&g_part[((size_t)seg * 2048 + j) * Bc + 4 * bq] = v;
            }
            __threadfence();
            __syncthreads();
            if (tid == 0) {
                int old = atomicAdd(&g_cnt[chunk], 1);
                slast = (old == 7) ? 1 : 0;
            }
            __syncthreads();

            if (slast) {
                __threadfence();   // acquire: order partials reads after counter
                const float* bi = layer ? bih1 : bih0;
                const float* bh = layer ? bhh1 : bhh0;
                for (int p = tid; p < 1024; p += 256) {
                    int u = p >> 5, b = p & 31;
                    int hh = (chunk << 5) + u;
                    float gg[4];
                    #pragma unroll
                    for (int g = 0; g < 4; g++) {
                        int j = (g << 9) + hh;
                        float s = bi[j] + bh[j];
                        #pragma unroll
                        for (int sg = 0; sg < 8; sg++)
                            s += __ldcg(&g_part[((size_t)sg * 2048 + j) * Bc + b]);
                        gg[g] = s;
                    }
                    float* cptr = &g_c[layer][b * Hc + hh];
                    float cold = *cptr;   // chunk's last-block owns these cells
                    float i_ = 1.f / (1.f + expf(-gg[0]));
                    float f_ = 1.f / (1.f + expf(-gg[1]));
                    float gv = tanhf(gg[2]);
                    float o_ = 1.f / (1.f + expf(-gg[3]));
                    float cn = f_ * cold + i_ * gv;
                    float hn = o_ * tanhf(cn);
                    *cptr = cn;
                    if (layer == 0) {
                        g_h0T[nx][hh * Bc + b] = hn;
                    } else {
                        g_h1T[nx][hh * Bc + b] = hn;
                        g_concat[((size_t)(t * Bc + b)) * KC + hh] = hn;
                    }
                }
                if (tid == 0) g_cnt[chunk] = 0;   // self-reset
            }
            gbar(sense);
        }
    }
}

// ---------------- tensor-core vocab projection: split-bf16, 3-product ----------------
__device__ __forceinline__ void mma_bf16(float c[4], const uint32_t a[4], const uint32_t b[2]) {
    asm volatile("mma.sync.aligned.m16n8k16.row.col.f32.bf16.bf16.f32 "
                 "{%0,%1,%2,%3}, {%4,%5,%6,%7}, {%8,%9}, {%0,%1,%2,%3};"
                 : "+f"(c[0]), "+f"(c[1]), "+f"(c[2]), "+f"(c[3])
                 : "r"(a[0]), "r"(a[1]), "r"(a[2]), "r"(a[3]), "r"(b[0]), "r"(b[1]));
}

__global__ __launch_bounds__(256) void k_mma(const float* __restrict__ bias,
                                             float* __restrict__ out) {
    __shared__ __nv_bfloat16 As[2][64 * 48];
    __shared__ __nv_bfloat16 Bs[2][128 * 48];
    int m0 = blockIdx.x * 64;
    int n0 = blockIdx.y * 128;
    int tid = threadIdx.x, lane = tid & 31, wid = tid >> 5;
    int wm = wid & 1, wn = wid >> 1;
    int g = lane >> 2, q2 = (lane & 3) * 2;

    float acc[2][4][4];
    #pragma unroll
    for (int i = 0; i < 2; i++)
        #pragma unroll
        for (int j = 0; j < 4; j++)
            #pragma unroll
            for (int q = 0; q < 4; q++) acc[i][j][q] = 0.f;

    int arow = tid >> 2, akc = (tid & 3) * 8;

    for (int kt = 0; kt < KC / 32; kt++) {
        int k0 = kt * 32;
        *(uint4*)&As[0][arow * 48 + akc] = *(const uint4*)&g_Ahi[(size_t)(m0 + arow) * KC + k0 + akc];
        *(uint4*)&As[1][arow * 48 + akc] = *(const uint4*)&g_Alo[(size_t)(m0 + arow) * KC + k0 + akc];
        #pragma unroll
        for (int i = 0; i < 2; i++) {
            int idx = i * 256 + tid;
            int n = idx >> 2, kc = (idx & 3) * 8;
            *(uint4*)&Bs[0][n * 48 + kc] = *(const uint4*)&g_Whi[(size_t)(n0 + n) * KC + k0 + kc];
            *(uint4*)&Bs[1][n * 48 + kc] = *(const uint4*)&g_Wlo[(size_t)(n0 + n) * KC + k0 + kc];
        }
        __syncthreads();

        #pragma unroll
        for (int ks = 0; ks < 32; ks += 16) {
            uint32_t ah[2][4], al[2][4], bh[4][2], bl[4][2];
            #pragma unroll
            for (int m2 = 0; m2 < 2; m2++) {
                int rm = wm * 32 + m2 * 16;
                ah[m2][0] = *(uint32_t*)&As[0][(rm + g) * 48 + ks + q2];
                ah[m2][1] = *(uint32_t*)&As[0][(rm + 8 + g) * 48 + ks + q2];
                ah[m2][2] = *(uint32_t*)&As[0][(rm + g) * 48 + ks + 8 + q2];
                ah[m2][3] = *(uint32_t*)&As[0][(rm + 8 + g) * 48 + ks + 8 + q2];
                al[m2][0] = *(uint32_t*)&As[1][(rm + g) * 48 + ks + q2];
                al[m2][1] = *(uint32_t*)&As[1][(rm + 8 + g) * 48 + ks + q2];
                al[m2][2] = *(uint32_t*)&As[1][(rm + g) * 48 + ks + 8 + q2];
                al[m2][3] = *(uint32_t*)&As[1][(rm + 8 + g) * 48 + ks + 8 + q2];
            }
            #pragma unroll
            for (int n4 = 0; n4 < 4; n4++) {
                int cn = wn * 32 + n4 * 8;
                bh[n4][0] = *(uint32_t*)&Bs[0][(cn + g) * 48 + ks + q2];
                bh[n4][1] = *(uint32_t*)&Bs[0][(cn + g) * 48 + ks + 8 + q2];
                bl[n4][0] = *(uint32_t*)&Bs[1][(cn + g) * 48 + ks + q2];
                bl[n4][1] = *(uint32_t*)&Bs[1][(cn + g) * 48 + ks + 8 + q2];
            }
            #pragma unroll
            for (int m2 = 0; m2 < 2; m2++)
                #pragma unroll
                for (int n4 = 0; n4 < 4; n4++) {
                    mma_bf16(acc[m2][n4], ah[m2], bh[n4]);
                    mma_bf16(acc[m2][n4], ah[m2], bl[n4]);
                    mma_bf16(acc[m2][n4], al[m2], bh[n4]);
                }
        }
        __syncthreads();
    }

    #pragma unroll
    for (int m2 = 0; m2 < 2; m2++)
        #pragma unroll
        for (int n4 = 0; n4 < 4; n4++) {
            int gm = m0 + wm * 32 + m2 * 16 + g;
            int gn = n0 + wn * 32 + n4 * 8 + q2;
            float bb0 = bias[gn], bb1 = bias[gn + 1];
            int t0 = gm >> 5, b0 = gm & 31;
            float2 v0 = make_float2(acc[m2][n4][0] + bb0, acc[m2][n4][1] + bb1);
            *(float2*)&out[(size_t)b0 * Tc * Vc + (size_t)t0 * Vc + gn] = v0;
            int gm8 = gm + 8;
            int t1 = gm8 >> 5, b1 = gm8 & 31;
            float2 v1 = make_float2(acc[m2][n4][2] + bb0, acc[m2][n4][3] + bb1);
            *(float2*)&out[(size_t)b1 * Tc * Vc + (size_t)t1 * Vc + gn] = v1;
        }
}

// ---------------- final state copy (T even -> final h in buffer 0) ----------------
__global__ void k_final(float* __restrict__ out) {
    int i = blockIdx.x * blockDim.x + threadIdx.x;
    if (i < Bc * Hc) {
        int h = i & (Hc - 1), b = i >> 9;
        out[OFF_H + i] = g_h0T[0][h * Bc + b];
        out[OFF_H + Bc * Hc + i] = g_h1T[0][h * Bc + b];
        out[OFF_C + i] = g_c[0][i];
        out[OFF_C + Bc * Hc + i] = g_c[1][i];
    }
}

// ---------------- launch ----------------
extern "C" void kernel_launch(void* const* d_in, const int* in_sizes, int n_in,
                              void* d_out, int out_size) {
    int idx_emb = -1, idx_enc = -1, idx_h0 = -1;
    for (int i = 0; i < n_in; i++) {
        if (in_sizes[i] == 16384000) { idx_emb = i; break; }
    }
    for (int i = 0; i < n_in; i++) {
        if (in_sizes[i] == 1048576) { idx_enc = i; break; }
    }
    for (int i = 0; i < n_in; i++) {
        if (in_sizes[i] == 32768) { idx_h0 = i; break; }
    }
    const int*   tok  = (const int*)d_in[0];
    const float* enc  = (const float*)d_in[idx_enc];
    const float* h0   = (const float*)d_in[idx_h0];
    const float* c0   = (const float*)d_in[idx_h0 + 1];
    const float* emb  = (const float*)d_in[idx_emb];
    const float* Wih0 = (const float*)d_in[idx_emb + 1];
    const float* Whh0 = (const float*)d_in[idx_emb + 2];
    const float* bih0 = (const float*)d_in[idx_emb + 3];
    const float* bhh0 = (const float*)d_in[idx_emb + 4];
    const float* Wih1 = (const float*)d_in[idx_emb + 5];
    const float* Whh1 = (const float*)d_in[idx_emb + 6];
    const float* bih1 = (const float*)d_in[idx_emb + 7];
    const float* bhh1 = (const float*)d_in[idx_emb + 8];
    const float* fcW  = (const float*)d_in[idx_emb + 9];
    const float* fcb  = (const float*)d_in[idx_emb + 10];
    float* out = (float*)d_out;

    k_cvtW<<<48000, 256>>>(fcW);

    k_init<<<(Bc * Hc + 255) / 256, 256>>>(h0, c0);
    k_embed<<<Tc * Bc, 128>>>(tok, emb);    // concat emb section (for cvtA)
    k_embed2<<<Tc * Bc, 128>>>(tok, emb);   // transposed emb (for recurrence)

    // whole recurrence in ONE persistent kernel (128 CTAs, 3 barriers/step,
    // gates fused into partials phases via per-chunk last-block counters)
    k_recur<<<GRID_P, 256>>>(enc, Wih0, Whh0, bih0, bhh0,
                             Wih1, Whh1, bih1, bhh1, out);

    k_cvtA<<<3072, 256>>>();
    k_mma<<<dim3(Tc * Bc / 64, Vc / 128), 256>>>(fcb, out);
    k_final<<<(Bc * Hc + 255) / 256, 256>>>(out);
}

// round 16
// speedup vs baseline: 1.2020x; 1.1448x over previous
#include <cuda_runtime.h>
#include <cuda_bf16.h>
#include <math.h>
#include <stdint.h>
#include <stddef.h>

// Problem constants
#define Bc 32
#define Tc 64
#define Sc 64
#define Vc 32000
#define Ec 512
#define Hc 512
#define KC 1536   // concat width = 2H + E

#define GRID_P 128   // persistent CTAs (<=148 SMs -> all co-resident)

// Output layout offsets (floats): outputs (B,T,V), h (2,B,H), c (2,B,H), attn (B,T,S)
#define OFF_H   ((size_t)Bc * Tc * Vc)
#define OFF_C   (OFF_H + (size_t)2 * Bc * Hc)
#define OFF_ATT (OFF_C + (size_t)2 * Bc * Hc)

// ---------------- device scratch (no allocations allowed) ----------------
__device__ float g_concat[(size_t)Tc * Bc * KC];   // [t][b][ h1 | ctx | emb ]
__device__ float g_part[8 * 2048 * Bc];            // split-K partial gates
__device__ float g_c[2][Bc * Hc];                  // [layer][b*H+h]

// transposed [k][b] state for coalesced x-tile loads in the persistent kernel
__device__ float g_embT[Tc][Ec * Bc];
__device__ float g_ctxT[Hc * Bc];
__device__ float g_h0T[Hc * Bc];
__device__ float g_h1T[Hc * Bc];

// grid barrier state (sense-reversal; even barrier count per launch -> parity-safe)
__device__ int g_bar_cnt;
__device__ volatile int g_bar_sense;

// bf16 split operands for tensor-core vocab projection
__device__ __nv_bfloat16 g_Whi[(size_t)Vc * KC];
__device__ __nv_bfloat16 g_Wlo[(size_t)Vc * KC];
__device__ __nv_bfloat16 g_Ahi[(size_t)Tc * Bc * KC];
__device__ __nv_bfloat16 g_Alo[(size_t)Tc * Bc * KC];

// ---------------- init: copy h0/c0 into state buffers (transposed h) ----------------
__global__ void k_init(const float* __restrict__ h0, const float* __restrict__ c0) {
    int i = blockIdx.x * blockDim.x + threadIdx.x;
    if (i < Bc * Hc) {
        int h = i & (Hc - 1), b = i >> 9;
        g_h0T[h * Bc + b] = h0[i];
        g_h1T[h * Bc + b] = h0[Bc * Hc + i];
        g_c[0][i] = c0[i];
        g_c[1][i] = c0[Bc * Hc + i];
    }
}

// ---------------- embedding gathers ----------------
__global__ void k_embed(const int* __restrict__ tok, const float* __restrict__ emb) {
    int r = blockIdx.x;          // r = t*32 + b
    int t = r >> 5, b = r & 31;
    int tk = tok[b * Tc + t];
    const float4* src = (const float4*)(emb + (size_t)tk * Ec);
    float4* dst = (float4*)(g_concat + (size_t)r * KC + 2 * Hc);
    for (int i = threadIdx.x; i < Ec / 4; i += blockDim.x) dst[i] = src[i];
}

__global__ void k_embed2(const int* __restrict__ tok, const float* __restrict__ emb) {
    int r = blockIdx.x;          // r = t*32 + b
    int t = r >> 5, b = r & 31;
    int tk = tok[b * Tc + t];
    const float* src = emb + (size_t)tk * Ec;
    for (int k = threadIdx.x; k < Ec; k += blockDim.x)
        g_embT[t][k * Bc + b] = src[k];
}

// ---------------- split-bf16 conversion kernels ----------------
__global__ void k_cvtW(const float* __restrict__ src) {
    size_t i = ((size_t)blockIdx.x * 256 + threadIdx.x) * 4;
    float4 v = *(const float4*)(src + i);
    __nv_bfloat16 h0 = __float2bfloat16(v.x), h1 = __float2bfloat16(v.y);
    __nv_bfloat16 h2 = __float2bfloat16(v.z), h3 = __float2bfloat16(v.w);
    __nv_bfloat16 l0 = __float2bfloat16(v.x - __bfloat162float(h0));
    __nv_bfloat16 l1 = __float2bfloat16(v.y - __bfloat162float(h1));
    __nv_bfloat16 l2 = __float2bfloat16(v.z - __bfloat162float(h2));
    __nv_bfloat16 l3 = __float2bfloat16(v.w - __bfloat162float(h3));
    *(__nv_bfloat162*)&g_Whi[i]     = __halves2bfloat162(h0, h1);
    *(__nv_bfloat162*)&g_Whi[i + 2] = __halves2bfloat162(h2, h3);
    *(__nv_bfloat162*)&g_Wlo[i]     = __halves2bfloat162(l0, l1);
    *(__nv_bfloat162*)&g_Wlo[i + 2] = __halves2bfloat162(l2, l3);
}

__global__ void k_cvtA() {
    size_t i = ((size_t)blockIdx.x * 256 + threadIdx.x) * 4;
    float4 v = *(const float4*)(g_concat + i);
    __nv_bfloat16 h0 = __float2bfloat16(v.x), h1 = __float2bfloat16(v.y);
    __nv_bfloat16 h2 = __float2bfloat16(v.z), h3 = __float2bfloat16(v.w);
    __nv_bfloat16 l0 = __float2bfloat16(v.x - __bfloat162float(h0));
    __nv_bfloat16 l1 = __float2bfloat16(v.y - __bfloat162float(h1));
    __nv_bfloat16 l2 = __float2bfloat16(v.z - __bfloat162float(h2));
    __nv_bfloat16 l3 = __float2bfloat16(v.w - __bfloat162float(h3));
    *(__nv_bfloat162*)&g_Ahi[i]     = __halves2bfloat162(h0, h1);
    *(__nv_bfloat162*)&g_Ahi[i + 2] = __halves2bfloat162(h2, h3);
    *(__nv_bfloat162*)&g_Alo[i]     = __halves2bfloat162(l0, l1);
    *(__nv_bfloat162*)&g_Alo[i + 2] = __halves2bfloat162(l2, l3);
}

// ---------------- grid barrier: atomic arrive, VOLATILE-LOAD poll (the one change) ----------------
__device__ __forceinline__ void gbar(int& sense) {
    __syncthreads();
    if (threadIdx.x == 0) {
        __threadfence();                              // release
        int t = atomicAdd(&g_bar_cnt, 1);
        if (t == GRID_P - 1) {
            g_bar_cnt = 0;
            __threadfence();
            g_bar_sense = sense ^ 1;                  // volatile store (release)
        } else {
            while (g_bar_sense == sense) __nanosleep(64);  // parallel L2 reads, no RMW
        }
        __threadfence();                              // acquire
    }
    __syncthreads();
    sense ^= 1;
}

// ---------------- persistent recurrence kernel (R11 structure, unchanged) ----------------
// 128 CTAs x 256 threads. Per step: P1 attn (32 CTAs) | P2 L0 partials (16x8 jobs)
// | P3 L0 gates (all CTAs) | P4 L1 partials | P5 L1 gates. 5 grid barriers/step.
__global__ __launch_bounds__(256) void k_recur(
    const float* __restrict__ enc,
    const float* __restrict__ Wih0, const float* __restrict__ Whh0,
    const float* __restrict__ bih0, const float* __restrict__ bhh0,
    const float* __restrict__ Wih1, const float* __restrict__ Whh1,
    const float* __restrict__ bih1, const float* __restrict__ bhh1,
    float* __restrict__ out)
{
    __shared__ float xs[192 * 33];    // x tile [k][b] (layer0: 192 rows, layer1: 128)
    __shared__ float wsT[32 * 129];   // W sub-tile [k][j_local]; reused as q in P1
    __shared__ float sc[Sc];
    __shared__ float sa[Sc];

    const int bid = blockIdx.x;
    const int tid = threadIdx.x, w = tid >> 5, lane = tid & 31;
    const int bq = tid & 7;      // b-group (4 b each)
    const int jq = tid >> 3;     // j-group (4 j each, 0..31)
    const int chunk = bid & 15;  // 32 hidden units
    const int seg = bid >> 4;    // k-segment 0..7
    int sense = 0;

    for (int t = 0; t < Tc; t++) {
        // ---------- P1: attention (CTAs 0..31, b = bid) ----------
        if (bid < Bc) {
            int b = bid;
            float* qs = wsT;   // 512 floats
            for (int i = tid; i < Hc; i += 256) qs[i] = __ldcg(&g_h1T[i * Bc + b]);
            __syncthreads();
            const float* encb = enc + (size_t)b * Sc * Hc;
            #pragma unroll
            for (int i = 0; i < 8; i++) {
                int s = w * 8 + i;
                const float* e = encb + (size_t)s * Hc;
                float acc = 0.f;
                for (int h = lane; h < Hc; h += 32) acc += qs[h] * e[h];
                #pragma unroll
                for (int o = 16; o; o >>= 1) acc += __shfl_down_sync(0xffffffffu, acc, o);
                if (lane == 0) sc[s] = acc * 0.04419417382415922f;  // 1/sqrt(512)
            }
            __syncthreads();
            if (w == 0) {
                float v0 = sc[lane], v1 = sc[lane + 32];
                float m = fmaxf(v0, v1);
                #pragma unroll
                for (int o = 16; o; o >>= 1) m = fmaxf(m, __shfl_xor_sync(0xffffffffu, m, o));
                float e0 = expf(v0 - m), e1 = expf(v1 - m);
                float ssum = e0 + e1;
                #pragma unroll
                for (int o = 16; o; o >>= 1) ssum += __shfl_xor_sync(0xffffffffu, ssum, o);
                float inv = 1.f / ssum;
                sa[lane] = e0 * inv;
                sa[lane + 32] = e1 * inv;
            }
            __syncthreads();
            if (tid < Sc) out[OFF_ATT + (size_t)b * Tc * Sc + (size_t)t * Sc + tid] = sa[tid];
            for (int h = tid; h < Hc; h += 256) {
                float acc = 0.f;
                #pragma unroll 8
                for (int s = 0; s < Sc; s++) acc += sa[s] * encb[(size_t)s * Hc + h];
                g_ctxT[h * Bc + b] = acc;
                g_concat[((size_t)(t * Bc + b)) * KC + Hc + h] = acc;
            }
        }
        gbar(sense);

        // ---------- P2 / P4: split-K GEMM partials ----------
        #pragma unroll 1
        for (int layer = 0; layer < 2; layer++) {
            const int KSEG = (layer == 0) ? 192 : 128;
            const int k0 = seg * KSEG;
            // load x tile rows (coalesced: 32 consecutive b per k-row)
            for (int r = w; r < KSEG; r += 8) {
                int gk = k0 + r;
                const float* src;
                if (layer == 0) {
                    if (gk < Ec)            src = &g_embT[t][gk * Bc];
                    else if (gk < Ec + Hc)  src = &g_ctxT[(gk - Ec) * Bc];
                    else                    src = &g_h0T[(gk - Ec - Hc) * Bc];
                } else {
                    src = (gk < Hc) ? &g_h0T[gk * Bc] : &g_h1T[(gk - Hc) * Bc];
                }
                xs[r * 33 + lane] = __ldcg(&src[lane]);
            }

            float acc[4][4] = {};
            const float* Wih = layer ? Wih1 : Wih0;
            const float* Whh = layer ? Whh1 : Whh0;
            const int nkt = KSEG / 32;
            for (int kt = 0; kt < nkt; kt++) {
                __syncthreads();
                int gk = k0 + kt * 32;
                const float* wptr; int wstr;
                if (layer == 0) {
                    if (gk < Ec + Hc) { wptr = Wih + gk;            wstr = Ec + Hc; }
                    else              { wptr = Whh + (gk - Ec - Hc); wstr = Hc; }
                } else {
                    if (gk < Hc)      { wptr = Wih + gk;            wstr = Hc; }
                    else              { wptr = Whh + (gk - Hc);      wstr = Hc; }
                }
                #pragma unroll
                for (int i = 0; i < 16; i++) {
                    int jl = w * 16 + i;
                    int j = ((jl >> 5) << 9) + (chunk << 5) + (jl & 31);
                    wsT[lane * 129 + jl] = wptr[(size_t)j * wstr + lane];
                }
                __syncthreads();
                #pragma unroll
                for (int kk = 0; kk < 32; kk++) {
                    int kg = kt * 32 + kk;
                    float xv0 = xs[kg * 33 + 4 * bq + 0], xv1 = xs[kg * 33 + 4 * bq + 1];
                    float xv2 = xs[kg * 33 + 4 * bq + 2], xv3 = xs[kg * 33 + 4 * bq + 3];
                    float wv0 = wsT[kk * 129 + 4 * jq + 0], wv1 = wsT[kk * 129 + 4 * jq + 1];
                    float wv2 = wsT[kk * 129 + 4 * jq + 2], wv3 = wsT[kk * 129 + 4 * jq + 3];
                    acc[0][0] += wv0 * xv0; acc[0][1] += wv0 * xv1; acc[0][2] += wv0 * xv2; acc[0][3] += wv0 * xv3;
                    acc[1][0] += wv1 * xv0; acc[1][1] += wv1 * xv1; acc[1][2] += wv1 * xv2; acc[1][3] += wv1 * xv3;
                    acc[2][0] += wv2 * xv0; acc[2][1] += wv2 * xv1; acc[2][2] += wv2 * xv2; acc[2][3] += wv2 * xv3;
                    acc[3][0] += wv3 * xv0; acc[3][1] += wv3 * xv1; acc[3][2] += wv3 * xv2; acc[3][3] += wv3 * xv3;
                }
            }
            #pragma unroll
            for (int ji = 0; ji < 4; ji++) {
                int jl = 4 * jq + ji;
                int j = ((jl >> 5) << 9) + (chunk << 5) + (jl & 31);
                float4 v = make_float4(acc[ji][0], acc[ji][1], acc[ji][2], acc[ji][3]);
                *(float4*)&g_part[((size_t)seg * 2048 + j) * Bc + 4 * bq] = v;
            }
            __syncthreads();   // xs/wsT reuse safety before barrier
            gbar(sense);

            // ---------- P3 / P5: gate reduce + state update (128 cells/CTA, ALL CTAs) ----------
            if (tid < 128) {
                int cell = bid * 128 + tid;   // 16384 = 512h x 32b
                int h = cell >> 5, b = cell & 31;
                const float* bi = layer ? bih1 : bih0;
                const float* bh = layer ? bhh1 : bhh0;
                float gg[4];
                #pragma unroll
                for (int g = 0; g < 4; g++) {
                    int j = (g << 9) + h;
                    float s = bi[j] + bh[j];
                    #pragma unroll
                    for (int sg = 0; sg < 8; sg++)
                        s += __ldcg(&g_part[((size_t)sg * 2048 + j) * Bc + b]);
                    gg[g] = s;
                }
                float* cptr = &g_c[layer][b * Hc + h];
                float cold = *cptr;   // same CTA owns this cell every step
                float i_ = 1.f / (1.f + expf(-gg[0]));
                float f_ = 1.f / (1.f + expf(-gg[1]));
                float gv = tanhf(gg[2]);
                float o_ = 1.f / (1.f + expf(-gg[3]));
                float cn = f_ * cold + i_ * gv;
                float hn = o_ * tanhf(cn);
                *cptr = cn;
                if (layer == 0) {
                    g_h0T[h * Bc + b] = hn;
                } else {
                    g_h1T[h * Bc + b] = hn;
                    g_concat[((size_t)(t * Bc + b)) * KC + h] = hn;
                }
            }
            gbar(sense);
        }
    }
}

// ---------------- tensor-core vocab projection: split-bf16, 3-product ----------------
__device__ __forceinline__ void mma_bf16(float c[4], const uint32_t a[4], const uint32_t b[2]) {
    asm volatile("mma.sync.aligned.m16n8k16.row.col.f32.bf16.bf16.f32 "
                 "{%0,%1,%2,%3}, {%4,%5,%6,%7}, {%8,%9}, {%0,%1,%2,%3};"
                 : "+f"(c[0]), "+f"(c[1]), "+f"(c[2]), "+f"(c[3])
                 : "r"(a[0]), "r"(a[1]), "r"(a[2]), "r"(a[3]), "r"(b[0]), "r"(b[1]));
}

__global__ __launch_bounds__(256) void k_mma(const float* __restrict__ bias,
                                             float* __restrict__ out) {
    __shared__ __nv_bfloat16 As[2][64 * 48];
    __shared__ __nv_bfloat16 Bs[2][128 * 48];
    int m0 = blockIdx.x * 64;
    int n0 = blockIdx.y * 128;
    int tid = threadIdx.x, lane = tid & 31, wid = tid >> 5;
    int wm = wid & 1, wn = wid >> 1;
    int g = lane >> 2, q2 = (lane & 3) * 2;

    float acc[2][4][4];
    #pragma unroll
    for (int i = 0; i < 2; i++)
        #pragma unroll
        for (int j = 0; j < 4; j++)
            #pragma unroll
            for (int q = 0; q < 4; q++) acc[i][j][q] = 0.f;

    int arow = tid >> 2, akc = (tid & 3) * 8;

    for (int kt = 0; kt < KC / 32; kt++) {
        int k0 = kt * 32;
        *(uint4*)&As[0][arow * 48 + akc] = *(const uint4*)&g_Ahi[(size_t)(m0 + arow) * KC + k0 + akc];
        *(uint4*)&As[1][arow * 48 + akc] = *(const uint4*)&g_Alo[(size_t)(m0 + arow) * KC + k0 + akc];
        #pragma unroll
        for (int i = 0; i < 2; i++) {
            int idx = i * 256 + tid;
            int n = idx >> 2, kc = (idx & 3) * 8;
            *(uint4*)&Bs[0][n * 48 + kc] = *(const uint4*)&g_Whi[(size_t)(n0 + n) * KC + k0 + kc];
            *(uint4*)&Bs[1][n * 48 + kc] = *(const uint4*)&g_Wlo[(size_t)(n0 + n) * KC + k0 + kc];
        }
        __syncthreads();

        #pragma unroll
        for (int ks = 0; ks < 32; ks += 16) {
            uint32_t ah[2][4], al[2][4], bh[4][2], bl[4][2];
            #pragma unroll
            for (int m2 = 0; m2 < 2; m2++) {
                int rm = wm * 32 + m2 * 16;
                ah[m2][0] = *(uint32_t*)&As[0][(rm + g) * 48 + ks + q2];
                ah[m2][1] = *(uint32_t*)&As[0][(rm + 8 + g) * 48 + ks + q2];
                ah[m2][2] = *(uint32_t*)&As[0][(rm + g) * 48 + ks + 8 + q2];
                ah[m2][3] = *(uint32_t*)&As[0][(rm + 8 + g) * 48 + ks + 8 + q2];
                al[m2][0] = *(uint32_t*)&As[1][(rm + g) * 48 + ks + q2];
                al[m2][1] = *(uint32_t*)&As[1][(rm + 8 + g) * 48 + ks + q2];
                al[m2][2] = *(uint32_t*)&As[1][(rm + g) * 48 + ks + 8 + q2];
                al[m2][3] = *(uint32_t*)&As[1][(rm + 8 + g) * 48 + ks + 8 + q2];
            }
            #pragma unroll
            for (int n4 = 0; n4 < 4; n4++) {
                int cn = wn * 32 + n4 * 8;
                bh[n4][0] = *(uint32_t*)&Bs[0][(cn + g) * 48 + ks + q2];
                bh[n4][1] = *(uint32_t*)&Bs[0][(cn + g) * 48 + ks + 8 + q2];
                bl[n4][0] = *(uint32_t*)&Bs[1][(cn + g) * 48 + ks + q2];
                bl[n4][1] = *(uint32_t*)&Bs[1][(cn + g) * 48 + ks + 8 + q2];
            }
            #pragma unroll
            for (int m2 = 0; m2 < 2; m2++)
                #pragma unroll
                for (int n4 = 0; n4 < 4; n4++) {
                    mma_bf16(acc[m2][n4], ah[m2], bh[n4]);
                    mma_bf16(acc[m2][n4], ah[m2], bl[n4]);
                    mma_bf16(acc[m2][n4], al[m2], bh[n4]);
                }
        }
        __syncthreads();
    }

    #pragma unroll
    for (int m2 = 0; m2 < 2; m2++)
        #pragma unroll
        for (int n4 = 0; n4 < 4; n4++) {
            int gm = m0 + wm * 32 + m2 * 16 + g;
            int gn = n0 + wn * 32 + n4 * 8 + q2;
            float bb0 = bias[gn], bb1 = bias[gn + 1];
            int t0 = gm >> 5, b0 = gm & 31;
            float2 v0 = make_float2(acc[m2][n4][0] + bb0, acc[m2][n4][1] + bb1);
            *(float2*)&out[(size_t)b0 * Tc * Vc + (size_t)t0 * Vc + gn] = v0;
            int gm8 = gm + 8;
            int t1 = gm8 >> 5, b1 = gm8 & 31;
            float2 v1 = make_float2(acc[m2][n4][2] + bb0, acc[m2][n4][3] + bb1);
            *(float2*)&out[(size_t)b1 * Tc * Vc + (size_t)t1 * Vc + gn] = v1;
        }
}

// ---------------- final state copy ----------------
__global__ void k_final(float* __restrict__ out) {
    int i = blockIdx.x * blockDim.x + threadIdx.x;
    if (i < Bc * Hc) {
        int h = i & (Hc - 1), b = i >> 9;
        out[OFF_H + i] = g_h0T[h * Bc + b];
        out[OFF_H + Bc * Hc + i] = g_h1T[h * Bc + b];
        out[OFF_C + i] = g_c[0][i];
        out[OFF_C + Bc * Hc + i] = g_c[1][i];
    }
}

// ---------------- launch ----------------
extern "C" void kernel_launch(void* const* d_in, const int* in_sizes, int n_in,
                              void* d_out, int out_size) {
    int idx_emb = -1, idx_enc = -1, idx_h0 = -1;
    for (int i = 0; i < n_in; i++) {
        if (in_sizes[i] == 16384000) { idx_emb = i; break; }
    }
    for (int i = 0; i < n_in; i++) {
        if (in_sizes[i] == 1048576) { idx_enc = i; break; }
    }
    for (int i = 0; i < n_in; i++) {
        if (in_sizes[i] == 32768) { idx_h0 = i; break; }
    }
    const int*   tok  = (const int*)d_in[0];
    const float* enc  = (const float*)d_in[idx_enc];
    const float* h0   = (const float*)d_in[idx_h0];
    const float* c0   = (const float*)d_in[idx_h0 + 1];
    const float* emb  = (const float*)d_in[idx_emb];
    const float* Wih0 = (const float*)d_in[idx_emb + 1];
    const float* Whh0 = (const float*)d_in[idx_emb + 2];
    const float* bih0 = (const float*)d_in[idx_emb + 3];
    const float* bhh0 = (const float*)d_in[idx_emb + 4];
    const float* Wih1 = (const float*)d_in[idx_emb + 5];
    const float* Whh1 = (const float*)d_in[idx_emb + 6];
    const float* bih1 = (const float*)d_in[idx_emb + 7];
    const float* bhh1 = (const float*)d_in[idx_emb + 8];
    const float* fcW  = (const float*)d_in[idx_emb + 9];
    const float* fcb  = (const float*)d_in[idx_emb + 10];
    float* out = (float*)d_out;

    k_cvtW<<<48000, 256>>>(fcW);

    k_init<<<(Bc * Hc + 255) / 256, 256>>>(h0, c0);
    k_embed<<<Tc * Bc, 128>>>(tok, emb);    // concat emb section (for cvtA)
    k_embed2<<<Tc * Bc, 128>>>(tok, emb);   // transposed emb (for recurrence)

    // whole recurrence in ONE persistent kernel (128 co-resident CTAs, 5 barriers/step,
    // volatile-load poll barrier — the single variable vs R11)
    k_recur<<<GRID_P, 256>>>(enc, Wih0, Whh0, bih0, bhh0,
                             Wih1, Whh1, bih1, bhh1, out);

    k_cvtA<<<3072, 256>>>();
    k_mma<<<dim3(Tc * Bc / 64, Vc / 128), 256>>>(fcb, out);
    k_final<<<(Bc * Hc + 255) / 256, 256>>>(out);
}

// round 17
// speedup vs baseline: 1.2275x; 1.0212x over previous
#include <cuda_runtime.h>
#include <cuda_bf16.h>
#include <math.h>
#include <stdint.h>
#include <stddef.h>

// Problem constants
#define Bc 32
#define Tc 64
#define Sc 64
#define Vc 32000
#define Ec 512
#define Hc 512
#define KC 1536   // concat width = 2H + E

#define GRID_P 128   // persistent CTAs (<=148 SMs -> all co-resident)
#define NTH 512      // threads per CTA (16 warps -> 4 warps/SMSP for latency hiding)

// Output layout offsets (floats): outputs (B,T,V), h (2,B,H), c (2,B,H), attn (B,T,S)
#define OFF_H   ((size_t)Bc * Tc * Vc)
#define OFF_C   (OFF_H + (size_t)2 * Bc * Hc)
#define OFF_ATT (OFF_C + (size_t)2 * Bc * Hc)

// ---------------- device scratch (no allocations allowed) ----------------
__device__ float g_concat[(size_t)Tc * Bc * KC];   // [t][b][ h1 | ctx | emb ]
__device__ float g_part[8 * 2048 * Bc];            // split-K partial gates
__device__ float g_c[2][Bc * Hc];                  // [layer][b*H+h]

// transposed [k][b] state for coalesced x-tile loads in the persistent kernel
__device__ float g_embT[Tc][Ec * Bc];
__device__ float g_ctxT[Hc * Bc];
__device__ float g_h0T[Hc * Bc];
__device__ float g_h1T[Hc * Bc];

// grid barrier state (sense-reversal; even barrier count per launch -> parity-safe)
__device__ int g_bar_cnt;
__device__ volatile int g_bar_sense;

// bf16 split operands for tensor-core vocab projection
__device__ __nv_bfloat16 g_Whi[(size_t)Vc * KC];
__device__ __nv_bfloat16 g_Wlo[(size_t)Vc * KC];
__device__ __nv_bfloat16 g_Ahi[(size_t)Tc * Bc * KC];
__device__ __nv_bfloat16 g_Alo[(size_t)Tc * Bc * KC];

// ---------------- init: copy h0/c0 into state buffers (transposed h) ----------------
__global__ void k_init(const float* __restrict__ h0, const float* __restrict__ c0) {
    int i = blockIdx.x * blockDim.x + threadIdx.x;
    if (i < Bc * Hc) {
        int h = i & (Hc - 1), b = i >> 9;
        g_h0T[h * Bc + b] = h0[i];
        g_h1T[h * Bc + b] = h0[Bc * Hc + i];
        g_c[0][i] = c0[i];
        g_c[1][i] = c0[Bc * Hc + i];
    }
}

// ---------------- embedding gathers ----------------
__global__ void k_embed(const int* __restrict__ tok, const float* __restrict__ emb) {
    int r = blockIdx.x;          // r = t*32 + b
    int t = r >> 5, b = r & 31;
    int tk = tok[b * Tc + t];
    const float4* src = (const float4*)(emb + (size_t)tk * Ec);
    float4* dst = (float4*)(g_concat + (size_t)r * KC + 2 * Hc);
    for (int i = threadIdx.x; i < Ec / 4; i += blockDim.x) dst[i] = src[i];
}

__global__ void k_embed2(const int* __restrict__ tok, const float* __restrict__ emb) {
    int r = blockIdx.x;          // r = t*32 + b
    int t = r >> 5, b = r & 31;
    int tk = tok[b * Tc + t];
    const float* src = emb + (size_t)tk * Ec;
    for (int k = threadIdx.x; k < Ec; k += blockDim.x)
        g_embT[t][k * Bc + b] = src[k];
}

// ---------------- split-bf16 conversion kernels ----------------
__global__ void k_cvtW(const float* __restrict__ src) {
    size_t i = ((size_t)blockIdx.x * 256 + threadIdx.x) * 4;
    float4 v = *(const float4*)(src + i);
    __nv_bfloat16 h0 = __float2bfloat16(v.x), h1 = __float2bfloat16(v.y);
    __nv_bfloat16 h2 = __float2bfloat16(v.z), h3 = __float2bfloat16(v.w);
    __nv_bfloat16 l0 = __float2bfloat16(v.x - __bfloat162float(h0));
    __nv_bfloat16 l1 = __float2bfloat16(v.y - __bfloat162float(h1));
    __nv_bfloat16 l2 = __float2bfloat16(v.z - __bfloat162float(h2));
    __nv_bfloat16 l3 = __float2bfloat16(v.w - __bfloat162float(h3));
    *(__nv_bfloat162*)&g_Whi[i]     = __halves2bfloat162(h0, h1);
    *(__nv_bfloat162*)&g_Whi[i + 2] = __halves2bfloat162(h2, h3);
    *(__nv_bfloat162*)&g_Wlo[i]     = __halves2bfloat162(l0, l1);
    *(__nv_bfloat162*)&g_Wlo[i + 2] = __halves2bfloat162(l2, l3);
}

__global__ void k_cvtA() {
    size_t i = ((size_t)blockIdx.x * 256 + threadIdx.x) * 4;
    float4 v = *(const float4*)(g_concat + i);
    __nv_bfloat16 h0 = __float2bfloat16(v.x), h1 = __float2bfloat16(v.y);
    __nv_bfloat16 h2 = __float2bfloat16(v.z), h3 = __float2bfloat16(v.w);
    __nv_bfloat16 l0 = __float2bfloat16(v.x - __bfloat162float(h0));
    __nv_bfloat16 l1 = __float2bfloat16(v.y - __bfloat162float(h1));
    __nv_bfloat16 l2 = __float2bfloat16(v.z - __bfloat162float(h2));
    __nv_bfloat16 l3 = __float2bfloat16(v.w - __bfloat162float(h3));
    *(__nv_bfloat162*)&g_Ahi[i]     = __halves2bfloat162(h0, h1);
    *(__nv_bfloat162*)&g_Ahi[i + 2] = __halves2bfloat162(h2, h3);
    *(__nv_bfloat162*)&g_Alo[i]     = __halves2bfloat162(l0, l1);
    *(__nv_bfloat162*)&g_Alo[i + 2] = __halves2bfloat162(l2, l3);
}

// ---------------- grid barrier: atomic arrive, volatile-load poll ----------------
__device__ __forceinline__ void gbar(int& sense) {
    __syncthreads();
    if (threadIdx.x == 0) {
        __threadfence();                              // release
        int t = atomicAdd(&g_bar_cnt, 1);
        if (t == GRID_P - 1) {
            g_bar_cnt = 0;
            __threadfence();
            g_bar_sense = sense ^ 1;                  // volatile store (release)
        } else {
            while (g_bar_sense == sense) __nanosleep(64);  // parallel L2 reads, no RMW
        }
        __threadfence();                              // acquire
    }
    __syncthreads();
    sense ^= 1;
}

// ---------------- persistent recurrence kernel ----------------
// 128 CTAs x 512 threads (16 warps/SM). Same phase/job layout as R11/R16:
// P1 attn (32 CTAs) | P2 L0 partials | P3 L0 gates | P4 L1 partials | P5 L1 gates.
// Per-thread compute tile is 2j x 4b (work conserved); 4 warps/SMSP hide
// LDS/L2/FFMA latency that 2 warps/SMSP could not.
__global__ __launch_bounds__(NTH) void k_recur(
    const float* __restrict__ enc,
    const float* __restrict__ Wih0, const float* __restrict__ Whh0,
    const float* __restrict__ bih0, const float* __restrict__ bhh0,
    const float* __restrict__ Wih1, const float* __restrict__ Whh1,
    const float* __restrict__ bih1, const float* __restrict__ bhh1,
    float* __restrict__ out)
{
    __shared__ float xs[192 * 33];    // x tile [k][b] (layer0: 192 rows, layer1: 128)
    __shared__ float wsT[32 * 129];   // W sub-tile [k][j_local]; reused as q in P1
    __shared__ float sc[Sc];
    __shared__ float sa[Sc];

    const int bid = blockIdx.x;
    const int tid = threadIdx.x, w = tid >> 5, lane = tid & 31;
    const int bq = tid & 7;      // b-group (4 b each)
    const int jq = tid >> 3;     // j-group (2 j each, 0..63)
    const int chunk = bid & 15;  // 32 hidden units
    const int seg = bid >> 4;    // k-segment 0..7
    int sense = 0;

    for (int t = 0; t < Tc; t++) {
        // ---------- P1: attention (CTAs 0..31, b = bid) ----------
        if (bid < Bc) {
            int b = bid;
            float* qs = wsT;   // 512 floats
            for (int i = tid; i < Hc; i += NTH) qs[i] = __ldcg(&g_h1T[i * Bc + b]);
            __syncthreads();
            const float* encb = enc + (size_t)b * Sc * Hc;
            #pragma unroll
            for (int i = 0; i < 4; i++) {
                int s = w * 4 + i;
                const float* e = encb + (size_t)s * Hc;
                float acc = 0.f;
                for (int h = lane; h < Hc; h += 32) acc += qs[h] * e[h];
                #pragma unroll
                for (int o = 16; o; o >>= 1) acc += __shfl_down_sync(0xffffffffu, acc, o);
                if (lane == 0) sc[s] = acc * 0.04419417382415922f;  // 1/sqrt(512)
            }
            __syncthreads();
            if (w == 0) {
                float v0 = sc[lane], v1 = sc[lane + 32];
                float m = fmaxf(v0, v1);
                #pragma unroll
                for (int o = 16; o; o >>= 1) m = fmaxf(m, __shfl_xor_sync(0xffffffffu, m, o));
                float e0 = expf(v0 - m), e1 = expf(v1 - m);
                float ssum = e0 + e1;
                #pragma unroll
                for (int o = 16; o; o >>= 1) ssum += __shfl_xor_sync(0xffffffffu, ssum, o);
                float inv = 1.f / ssum;
                sa[lane] = e0 * inv;
                sa[lane + 32] = e1 * inv;
            }
            __syncthreads();
            if (tid < Sc) out[OFF_ATT + (size_t)b * Tc * Sc + (size_t)t * Sc + tid] = sa[tid];
            for (int h = tid; h < Hc; h += NTH) {
                float acc = 0.f;
                #pragma unroll 8
                for (int s = 0; s < Sc; s++) acc += sa[s] * encb[(size_t)s * Hc + h];
                g_ctxT[h * Bc + b] = acc;
                g_concat[((size_t)(t * Bc + b)) * KC + Hc + h] = acc;
            }
        }
        gbar(sense);

        // ---------- P2 / P4: split-K GEMM partials ----------
        #pragma unroll 1
        for (int layer = 0; layer < 2; layer++) {
            const int KSEG = (layer == 0) ? 192 : 128;
            const int k0 = seg * KSEG;
            // load x tile rows (coalesced: 32 consecutive b per k-row)
            for (int r = w; r < KSEG; r += 16) {
                int gk = k0 + r;
                const float* src;
                if (layer == 0) {
                    if (gk < Ec)            src = &g_embT[t][gk * Bc];
                    else if (gk < Ec + Hc)  src = &g_ctxT[(gk - Ec) * Bc];
                    else                    src = &g_h0T[(gk - Ec - Hc) * Bc];
                } else {
                    src = (gk < Hc) ? &g_h0T[gk * Bc] : &g_h1T[(gk - Hc) * Bc];
                }
                xs[r * 33 + lane] = __ldcg(&src[lane]);
            }

            float acc[2][4] = {};
            const float* Wih = layer ? Wih1 : Wih0;
            const float* Whh = layer ? Whh1 : Whh0;
            const int nkt = KSEG / 32;
            for (int kt = 0; kt < nkt; kt++) {
                __syncthreads();
                int gk = k0 + kt * 32;
                const float* wptr; int wstr;
                if (layer == 0) {
                    if (gk < Ec + Hc) { wptr = Wih + gk;            wstr = Ec + Hc; }
                    else              { wptr = Whh + (gk - Ec - Hc); wstr = Hc; }
                } else {
                    if (gk < Hc)      { wptr = Wih + gk;            wstr = Hc; }
                    else              { wptr = Whh + (gk - Hc);      wstr = Hc; }
                }
                // 16 warps x 8 j-rows = 128 j rows of 32 k each
                #pragma unroll
                for (int i = 0; i < 8; i++) {
                    int jl = w * 8 + i;
                    int j = ((jl >> 5) << 9) + (chunk << 5) + (jl & 31);
                    wsT[lane * 129 + jl] = wptr[(size_t)j * wstr + lane];
                }
                __syncthreads();
                #pragma unroll
                for (int kk = 0; kk < 32; kk++) {
                    int kg = kt * 32 + kk;
                    float xv0 = xs[kg * 33 + 4 * bq + 0], xv1 = xs[kg * 33 + 4 * bq + 1];
                    float xv2 = xs[kg * 33 + 4 * bq + 2], xv3 = xs[kg * 33 + 4 * bq + 3];
                    float wv0 = wsT[kk * 129 + 2 * jq + 0], wv1 = wsT[kk * 129 + 2 * jq + 1];
                    acc[0][0] += wv0 * xv0; acc[0][1] += wv0 * xv1; acc[0][2] += wv0 * xv2; acc[0][3] += wv0 * xv3;
                    acc[1][0] += wv1 * xv0; acc[1][1] += wv1 * xv1; acc[1][2] += wv1 * xv2; acc[1][3] += wv1 * xv3;
                }
            }
            #pragma unroll
            for (int ji = 0; ji < 2; ji++) {
                int jl = 2 * jq + ji;
                int j = ((jl >> 5) << 9) + (chunk << 5) + (jl & 31);
                float4 v = make_float4(acc[ji][0], acc[ji][1], acc[ji][2], acc[ji][3]);
                *(float4*)&g_part[((size_t)seg * 2048 + j) * Bc + 4 * bq] = v;
            }
            __syncthreads();   // xs/wsT reuse safety before barrier
            gbar(sense);

            // ---------- P3 / P5: gate reduce + state update (128 cells/CTA, ALL CTAs) ----------
            if (tid < 128) {
                int cell = bid * 128 + tid;   // 16384 = 512h x 32b
                int h = cell >> 5, b = cell & 31;
                const float* bi = layer ? bih1 : bih0;
                const float* bh = layer ? bhh1 : bhh0;
                float gg[4];
                #pragma unroll
                for (int g = 0; g < 4; g++) {
                    int j = (g << 9) + h;
                    float s = bi[j] + bh[j];
                    #pragma unroll
                    for (int sg = 0; sg < 8; sg++)
                        s += __ldcg(&g_part[((size_t)sg * 2048 + j) * Bc + b]);
                    gg[g] = s;
                }
                float* cptr = &g_c[layer][b * Hc + h];
                float cold = *cptr;   // same CTA owns this cell every step
                float i_ = 1.f / (1.f + expf(-gg[0]));
                float f_ = 1.f / (1.f + expf(-gg[1]));
                float gv = tanhf(gg[2]);
                float o_ = 1.f / (1.f + expf(-gg[3]));
                float cn = f_ * cold + i_ * gv;
                float hn = o_ * tanhf(cn);
                *cptr = cn;
                if (layer == 0) {
                    g_h0T[h * Bc + b] = hn;
                } else {
                    g_h1T[h * Bc + b] = hn;
                    g_concat[((size_t)(t * Bc + b)) * KC + h] = hn;
                }
            }
            gbar(sense);
        }
    }
}

// ---------------- tensor-core vocab projection: split-bf16, 3-product ----------------
__device__ __forceinline__ void mma_bf16(float c[4], const uint32_t a[4], const uint32_t b[2]) {
    asm volatile("mma.sync.aligned.m16n8k16.row.col.f32.bf16.bf16.f32 "
                 "{%0,%1,%2,%3}, {%4,%5,%6,%7}, {%8,%9}, {%0,%1,%2,%3};"
                 : "+f"(c[0]), "+f"(c[1]), "+f"(c[2]), "+f"(c[3])
                 : "r"(a[0]), "r"(a[1]), "r"(a[2]), "r"(a[3]), "r"(b[0]), "r"(b[1]));
}

__global__ __launch_bounds__(256) void k_mma(const float* __restrict__ bias,
                                             float* __restrict__ out) {
    __shared__ __nv_bfloat16 As[2][64 * 48];
    __shared__ __nv_bfloat16 Bs[2][128 * 48];
    int m0 = blockIdx.x * 64;
    int n0 = blockIdx.y * 128;
    int tid = threadIdx.x, lane = tid & 31, wid = tid >> 5;
    int wm = wid & 1, wn = wid >> 1;
    int g = lane >> 2, q2 = (lane & 3) * 2;

    float acc[2][4][4];
    #pragma unroll
    for (int i = 0; i < 2; i++)
        #pragma unroll
        for (int j = 0; j < 4; j++)
            #pragma unroll
            for (int q = 0; q < 4; q++) acc[i][j][q] = 0.f;

    int arow = tid >> 2, akc = (tid & 3) * 8;

    for (int kt = 0; kt < KC / 32; kt++) {
        int k0 = kt * 32;
        *(uint4*)&As[0][arow * 48 + akc] = *(const uint4*)&g_Ahi[(size_t)(m0 + arow) * KC + k0 + akc];
        *(uint4*)&As[1][arow * 48 + akc] = *(const uint4*)&g_Alo[(size_t)(m0 + arow) * KC + k0 + akc];
        #pragma unroll
        for (int i = 0; i < 2; i++) {
            int idx = i * 256 + tid;
            int n = idx >> 2, kc = (idx & 3) * 8;
            *(uint4*)&Bs[0][n * 48 + kc] = *(const uint4*)&g_Whi[(size_t)(n0 + n) * KC + k0 + kc];
            *(uint4*)&Bs[1][n * 48 + kc] = *(const uint4*)&g_Wlo[(size_t)(n0 + n) * KC + k0 + kc];
        }
        __syncthreads();

        #pragma unroll
        for (int ks = 0; ks < 32; ks += 16) {
            uint32_t ah[2][4], al[2][4], bh[4][2], bl[4][2];
            #pragma unroll
            for (int m2 = 0; m2 < 2; m2++) {
                int rm = wm * 32 + m2 * 16;
                ah[m2][0] = *(uint32_t*)&As[0][(rm + g) * 48 + ks + q2];
                ah[m2][1] = *(uint32_t*)&As[0][(rm + 8 + g) * 48 + ks + q2];
                ah[m2][2] = *(uint32_t*)&As[0][(rm + g) * 48 + ks + 8 + q2];
                ah[m2][3] = *(uint32_t*)&As[0][(rm + 8 + g) * 48 + ks + 8 + q2];
                al[m2][0] = *(uint32_t*)&As[1][(rm + g) * 48 + ks + q2];
                al[m2][1] = *(uint32_t*)&As[1][(rm + 8 + g) * 48 + ks + q2];
                al[m2][2] = *(uint32_t*)&As[1][(rm + g) * 48 + ks + 8 + q2];
                al[m2][3] = *(uint32_t*)&As[1][(rm + 8 + g) * 48 + ks + 8 + q2];
            }
            #pragma unroll
            for (int n4 = 0; n4 < 4; n4++) {
                int cn = wn * 32 + n4 * 8;
                bh[n4][0] = *(uint32_t*)&Bs[0][(cn + g) * 48 + ks + q2];
                bh[n4][1] = *(uint32_t*)&Bs[0][(cn + g) * 48 + ks + 8 + q2];
                bl[n4][0] = *(uint32_t*)&Bs[1][(cn + g) * 48 + ks + q2];
                bl[n4][1] = *(uint32_t*)&Bs[1][(cn + g) * 48 + ks + 8 + q2];
            }
            #pragma unroll
            for (int m2 = 0; m2 < 2; m2++)
                #pragma unroll
                for (int n4 = 0; n4 < 4; n4++) {
                    mma_bf16(acc[m2][n4], ah[m2], bh[n4]);
                    mma_bf16(acc[m2][n4], ah[m2], bl[n4]);
                    mma_bf16(acc[m2][n4], al[m2], bh[n4]);
                }
        }
        __syncthreads();
    }

    #pragma unroll
    for (int m2 = 0; m2 < 2; m2++)
        #pragma unroll
        for (int n4 = 0; n4 < 4; n4++) {
            int gm = m0 + wm * 32 + m2 * 16 + g;
            int gn = n0 + wn * 32 + n4 * 8 + q2;
            float bb0 = bias[gn], bb1 = bias[gn + 1];
            int t0 = gm >> 5, b0 = gm & 31;
            float2 v0 = make_float2(acc[m2][n4][0] + bb0, acc[m2][n4][1] + bb1);
            *(float2*)&out[(size_t)b0 * Tc * Vc + (size_t)t0 * Vc + gn] = v0;
            int gm8 = gm + 8;
            int t1 = gm8 >> 5, b1 = gm8 & 31;
            float2 v1 = make_float2(acc[m2][n4][2] + bb0, acc[m2][n4][3] + bb1);
            *(float2*)&out[(size_t)b1 * Tc * Vc + (size_t)t1 * Vc + gn] = v1;
        }
}

// ---------------- final state copy ----------------
__global__ void k_final(float* __restrict__ out) {
    int i = blockIdx.x * blockDim.x + threadIdx.x;
    if (i < Bc * Hc) {
        int h = i & (Hc - 1), b = i >> 9;
        out[OFF_H + i] = g_h0T[h * Bc + b];
        out[OFF_H + Bc * Hc + i] = g_h1T[h * Bc + b];
        out[OFF_C + i] = g_c[0][i];
        out[OFF_C + Bc * Hc + i] = g_c[1][i];
    }
}

// ---------------- launch ----------------
extern "C" void kernel_launch(void* const* d_in, const int* in_sizes, int n_in,
                              void* d_out, int out_size) {
    int idx_emb = -1, idx_enc = -1, idx_h0 = -1;
    for (int i = 0; i < n_in; i++) {
        if (in_sizes[i] == 16384000) { idx_emb = i; break; }
    }
    for (int i = 0; i < n_in; i++) {
        if (in_sizes[i] == 1048576) { idx_enc = i; break; }
    }
    for (int i = 0; i < n_in; i++) {
        if (in_sizes[i] == 32768) { idx_h0 = i; break; }
    }
    const int*   tok  = (const int*)d_in[0];
    const float* enc  = (const float*)d_in[idx_enc];
    const float* h0   = (const float*)d_in[idx_h0];
    const float* c0   = (const float*)d_in[idx_h0 + 1];
    const float* emb  = (const float*)d_in[idx_emb];
    const float* Wih0 = (const float*)d_in[idx_emb + 1];
    const float* Whh0 = (const float*)d_in[idx_emb + 2];
    const float* bih0 = (const float*)d_in[idx_emb + 3];
    const float* bhh0 = (const float*)d_in[idx_emb + 4];
    const float* Wih1 = (const float*)d_in[idx_emb + 5];
    const float* Whh1 = (const float*)d_in[idx_emb + 6];
    const float* bih1 = (const float*)d_in[idx_emb + 7];
    const float* bhh1 = (const float*)d_in[idx_emb + 8];
    const float* fcW  = (const float*)d_in[idx_emb + 9];
    const float* fcb  = (const float*)d_in[idx_emb + 10];
    float* out = (float*)d_out;

    // NOTE: launch order arranged so k_recur is the 4th launch — the slot the
    // ncu capture window lands on — to get a real profile of the bottleneck.
    k_init<<<(Bc * Hc + 255) / 256, 256>>>(h0, c0);
    k_embed<<<Tc * Bc, 128>>>(tok, emb);    // concat emb section (for cvtA)
    k_embed2<<<Tc * Bc, 128>>>(tok, emb);   // transposed emb (for recurrence)

    // whole recurrence in ONE persistent kernel (128 CTAs x 512 threads)
    k_recur<<<GRID_P, NTH>>>(enc, Wih0, Whh0, bih0, bhh0,
                             Wih1, Whh1, bih1, bhh1, out);

    k_cvtW<<<48000, 256>>>(fcW);            // moved after recurrence (only k_mma needs it)
    k_cvtA<<<3072, 256>>>();
    k_mma<<<dim3(Tc * Bc / 64, Vc / 128), 256>>>(fcb, out);
    k_final<<<(Bc * Hc + 255) / 256, 256>>>(out);
}